// round 6
// baseline (speedup 1.0000x reference)
#include <cuda_runtime.h>
#include <cuda_fp16.h>

#define FD 128
#define NH 4
#define NN_MAX 50000
#define NE_MAX 800000
#define BM 128
#define LDX 132   // padded x-tile stride (kills row-load bank conflicts)

// Scratch (device globals: allocation-free per harness rules)
__device__ __half g_feat_h[NN_MAX * FD];  // projected features, fp16 (gather traffic /2)
__device__ float  g_el[NN_MAX * NH];
__device__ float  g_er[NN_MAX * NH];
__device__ float  g_wt[FD * FD];          // W transposed: g_wt[k][o]
__device__ int    g_rowstart[NN_MAX + 1];

// ---------------------------------------------------------------------------
// f32x2 packed helpers (FFMA2)
// ---------------------------------------------------------------------------
__device__ __forceinline__ void ffma2(unsigned long long& d,
                                      unsigned long long a,
                                      unsigned long long b) {
    asm("fma.rn.f32x2 %0, %1, %2, %0;" : "+l"(d) : "l"(a), "l"(b));
}
__device__ __forceinline__ unsigned long long pk2(float a) {
    unsigned long long r;
    asm("mov.b64 %0, {%1, %2};" : "=l"(r) : "f"(a), "f"(a));
    return r;
}
__device__ __forceinline__ float2 upk(unsigned long long v) {
    float2 r;
    asm("mov.b64 {%0, %1}, %2;" : "=f"(r.x), "=f"(r.y) : "l"(v));
    return r;
}
__device__ __forceinline__ unsigned pkh2(float a, float b) {
    __half2 h = __floats2half2_rn(a, b);   // low = a, high = b
    return *(unsigned*)&h;
}

// ---------------------------------------------------------------------------
// Kernel 0a: transpose W (128x128) once.
// ---------------------------------------------------------------------------
__global__ void gat_wt(const float* __restrict__ W) {
    __shared__ float t[32][33];
    int bx = blockIdx.x * 32, by = blockIdx.y * 32;
#pragma unroll
    for (int j = 0; j < 32; j += 8)
        t[threadIdx.y + j][threadIdx.x] = W[(by + threadIdx.y + j) * FD + bx + threadIdx.x];
    __syncthreads();
#pragma unroll
    for (int j = 0; j < 32; j += 8)
        g_wt[(bx + threadIdx.y + j) * FD + by + threadIdx.x] = t[threadIdx.x][threadIdx.y + j];
}

// ---------------------------------------------------------------------------
// Kernel 0b: segment starts from sorted dst.
// ---------------------------------------------------------------------------
__global__ void gat_seg(const int* __restrict__ dst, int n_edges, int n_nodes) {
    int i = blockIdx.x * blockDim.x + threadIdx.x;
    if (i < n_edges) {
        int d = dst[i];
        int prev = (i == 0) ? -1 : dst[i - 1];
        for (int n = prev + 1; n <= d; ++n) g_rowstart[n] = i;
        if (i == n_edges - 1)
            for (int n = d + 1; n <= n_nodes; ++n) g_rowstart[n] = n_edges;
    }
}

// ---------------------------------------------------------------------------
// Kernel 1: feat = x @ W^T. BM=128 x 128, K=128 resident. 256 threads,
// each computes 4 rows x 16 cols (32 FFMA2/k) -> FMA-pipe bound, not LDS.
// Epilogue: fp16 feat store + fused el/er (pair shfl reduction).
// ---------------------------------------------------------------------------
__global__ void __launch_bounds__(256) gat_gemm(
    const float* __restrict__ x,
    const float* __restrict__ al, const float* __restrict__ ar, int n_nodes)
{
    extern __shared__ float smem[];
    float* xs  = smem;                   // [128][LDX]
    float* ws  = smem + BM * LDX;        // [128][128] (k-major W^T)
    float* als = ws + FD * FD;
    float* ars = als + FD;

    const int tid = threadIdx.x;
    const int rb = blockIdx.x * BM;

    for (int p = tid; p < FD * FD / 4; p += 256)
        ((float4*)ws)[p] = ((const float4*)g_wt)[p];
    for (int p = tid; p < BM * 32; p += 256) {
        int r = p >> 5, k4 = p & 31;
        int gr = rb + r; if (gr >= n_nodes) gr = n_nodes - 1;
        *(float4*)(xs + r * LDX + k4 * 4) = *(const float4*)(x + gr * FD + k4 * 4);
    }
    if (tid < FD) { als[tid] = al[tid]; ars[tid] = ar[tid]; }
    __syncthreads();

    const int tx = tid & 7;              // 16 cols at tx*16
    const int ty = tid >> 3;             // 4 rows at ty*4
    const float* xr = xs + (ty * 4) * LDX;
    const ulonglong2* wrow = (const ulonglong2*)(ws + tx * 16);

    unsigned long long acc[4][8];
#pragma unroll
    for (int j = 0; j < 4; ++j)
#pragma unroll
        for (int p = 0; p < 8; ++p) acc[j][p] = 0ull;

#pragma unroll 4
    for (int k = 0; k < FD; ++k) {
        unsigned long long r0 = pk2(xr[k]);
        unsigned long long r1 = pk2(xr[LDX + k]);
        unsigned long long r2 = pk2(xr[2 * LDX + k]);
        unsigned long long r3 = pk2(xr[3 * LDX + k]);
        const ulonglong2* wp = (const ulonglong2*)((const char*)wrow + (size_t)k * FD * 4);
        ulonglong2 c0 = wp[0], c1 = wp[1], c2 = wp[2], c3 = wp[3];
        ffma2(acc[0][0], r0, c0.x); ffma2(acc[0][1], r0, c0.y);
        ffma2(acc[0][2], r0, c1.x); ffma2(acc[0][3], r0, c1.y);
        ffma2(acc[0][4], r0, c2.x); ffma2(acc[0][5], r0, c2.y);
        ffma2(acc[0][6], r0, c3.x); ffma2(acc[0][7], r0, c3.y);
        ffma2(acc[1][0], r1, c0.x); ffma2(acc[1][1], r1, c0.y);
        ffma2(acc[1][2], r1, c1.x); ffma2(acc[1][3], r1, c1.y);
        ffma2(acc[1][4], r1, c2.x); ffma2(acc[1][5], r1, c2.y);
        ffma2(acc[1][6], r1, c3.x); ffma2(acc[1][7], r1, c3.y);
        ffma2(acc[2][0], r2, c0.x); ffma2(acc[2][1], r2, c0.y);
        ffma2(acc[2][2], r2, c1.x); ffma2(acc[2][3], r2, c1.y);
        ffma2(acc[2][4], r2, c2.x); ffma2(acc[2][5], r2, c2.y);
        ffma2(acc[2][6], r2, c3.x); ffma2(acc[2][7], r2, c3.y);
        ffma2(acc[3][0], r3, c0.x); ffma2(acc[3][1], r3, c0.y);
        ffma2(acc[3][2], r3, c1.x); ffma2(acc[3][3], r3, c1.y);
        ffma2(acc[3][4], r3, c2.x); ffma2(acc[3][5], r3, c2.y);
        ffma2(acc[3][6], r3, c3.x); ffma2(acc[3][7], r3, c3.y);
    }

    // Epilogue
    const unsigned FULL = 0xffffffffu;
    const int lane = tid & 31;
    const int head = tx >> 1;            // my 16 cols lie entirely in this head

#pragma unroll
    for (int j = 0; j < 4; ++j) {
        int row = rb + ty * 4 + j;
        bool ok = row < n_nodes;
        float v[16];
#pragma unroll
        for (int p = 0; p < 8; ++p) {
            float2 f = upk(acc[j][p]);
            v[2 * p] = f.x; v[2 * p + 1] = f.y;
        }
        if (ok) {
            uint4 o0, o1;
            o0.x = pkh2(v[0],  v[1]);  o0.y = pkh2(v[2],  v[3]);
            o0.z = pkh2(v[4],  v[5]);  o0.w = pkh2(v[6],  v[7]);
            o1.x = pkh2(v[8],  v[9]);  o1.y = pkh2(v[10], v[11]);
            o1.z = pkh2(v[12], v[13]); o1.w = pkh2(v[14], v[15]);
            *(uint4*)(g_feat_h + row * FD + tx * 16)     = o0;
            *(uint4*)(g_feat_h + row * FD + tx * 16 + 8) = o1;
        }
        float pl = 0.f, pr = 0.f;
#pragma unroll
        for (int q = 0; q < 16; ++q) {
            float a = als[tx * 16 + q], b = ars[tx * 16 + q];
            pl = fmaf(v[q], a, pl);
            pr = fmaf(v[q], b, pr);
        }
        pl += __shfl_xor_sync(FULL, pl, 1);
        pr += __shfl_xor_sync(FULL, pr, 1);
        if (ok && !(lane & 1)) {
            g_el[row * NH + head] = pl;
            g_er[row * NH + head] = pr;
        }
    }
}

// ---------------------------------------------------------------------------
// Kernel 2: single-pass softmax + aggregation. One warp per dst node.
// feat gathered in fp16 (8B/lane, 256B/edge -> half the LTS traffic).
// ---------------------------------------------------------------------------
__global__ void __launch_bounds__(256) gat_agg(
    const int* __restrict__ src, float* __restrict__ out, int n_nodes)
{
    const int lane = threadIdx.x & 31;
    const int n = (blockIdx.x * blockDim.x + threadIdx.x) >> 5;
    if (n >= n_nodes) return;

    const int s = g_rowstart[n];
    const int e = g_rowstart[n + 1];
    const int h = lane >> 3;
    const float ern = g_er[n * NH + h];

    float denom = 0.f;
    float ax = 0.f, ay = 0.f, az = 0.f, aw = 0.f;

#pragma unroll 4
    for (int i = s; i < e; ++i) {
        int sv = __ldg(src + i);
        float lg = __ldg(g_el + sv * NH + h) + ern;
        lg = lg > 0.f ? lg : 0.2f * lg;
        float w = __expf(lg);
        denom += w;
        uint2 u = *(const uint2*)(g_feat_h + sv * FD + lane * 4);
        float2 f01 = __half22float2(*(__half2*)&u.x);
        float2 f23 = __half22float2(*(__half2*)&u.y);
        ax = fmaf(w, f01.x, ax); ay = fmaf(w, f01.y, ay);
        az = fmaf(w, f23.x, az); aw = fmaf(w, f23.y, aw);
    }
    float r = (e > s) ? 1.0f / denom : 0.f;
    *(float4*)(out + n * FD + lane * 4) =
        make_float4(ax * r, ay * r, az * r, aw * r);
}

// ---------------------------------------------------------------------------
extern "C" void kernel_launch(void* const* d_in, const int* in_sizes, int n_in,
                              void* d_out, int out_size)
{
    const float* x   = (const float*)d_in[0];
    const float* W   = (const float*)d_in[1];
    const float* al  = (const float*)d_in[2];
    const float* ar  = (const float*)d_in[3];
    const int*   src = (const int*)d_in[4];
    const int*   dst = (const int*)d_in[5];
    float* out = (float*)d_out;

    const int n_nodes = in_sizes[0] / FD;
    const int n_edges = in_sizes[4];

    gat_wt<<<dim3(4, 4), dim3(32, 8)>>>(W);
    gat_seg<<<(n_edges + 255) / 256, 256>>>(dst, n_edges, n_nodes);

    const size_t smem = (size_t)(BM * LDX + FD * FD + 2 * FD) * sizeof(float);
    cudaFuncSetAttribute(gat_gemm, cudaFuncAttributeMaxDynamicSharedMemorySize, (int)smem);
    gat_gemm<<<(n_nodes + BM - 1) / BM, 256, smem>>>(x, al, ar, n_nodes);

    gat_agg<<<(n_nodes * 32 + 255) / 256, 256>>>(src, out, n_nodes);
}

// round 8
// speedup vs baseline: 2.5316x; 2.5316x over previous
#include <cuda_runtime.h>
#include <cuda_bf16.h>
#include <cstdint>

#define FD 128
#define NH 4
#define NN_MAX 50000
#define NE_MAX 800000
#define BM 128
#define LDB 272            // padded smem row stride in BYTES (136 bf16) — bank-clean

// ---------------- device scratch (allocation-free) ----------------
__device__ float g_feat[NN_MAX * FD];
__device__ float g_el[NN_MAX * NH];
__device__ float g_er[NN_MAX * NH];
__device__ uint4 g_wbh4[FD * FD / 8];   // W hi bf16, row-major [n][k] (32KB)
__device__ uint4 g_wbl4[FD * FD / 8];   // W lo bf16
__device__ int   g_rowstart[NN_MAX + 1];

// smem byte offsets
#define SM_XH  0
#define SM_XL  (SM_XH + BM * LDB)       // 34816
#define SM_WH  (SM_XL + BM * LDB)       // 69632
#define SM_WL  (SM_WH + FD * LDB)       // 104448
#define SM_ALS (SM_WL + FD * LDB)       // 139264
#define SM_ARS (SM_ALS + 512)
#define SM_TOTAL (SM_ARS + 512)         // 140288 B

// ---------------- helpers ----------------
__device__ __forceinline__ uint32_t smem_u32(const void* p) {
    uint32_t a;
    asm("{ .reg .u64 t; cvta.to.shared.u64 t, %1; cvt.u32.u64 %0, t; }" : "=r"(a) : "l"(p));
    return a;
}
// fp32 pair -> packed bf16 hi word + lo (residual) word
__device__ __forceinline__ void split2(float a, float b, unsigned& hi, unsigned& lo) {
    __nv_bfloat162 h2 = __floats2bfloat162_rn(a, b);     // low=a, high=b
    float2 hf = __bfloat1622float2(h2);
    __nv_bfloat162 l2 = __floats2bfloat162_rn(a - hf.x, b - hf.y);
    hi = *(unsigned*)&h2;
    lo = *(unsigned*)&l2;
}
#define LDSM_X4(r0, r1, r2, r3, addr) \
    asm volatile("ldmatrix.sync.aligned.m8n8.x4.shared.b16 {%0,%1,%2,%3}, [%4];" \
                 : "=r"(r0), "=r"(r1), "=r"(r2), "=r"(r3) : "r"(addr))
#define MMA16816(d, a, b) \
    asm volatile("mma.sync.aligned.m16n8k16.row.col.f32.bf16.bf16.f32 " \
                 "{%0,%1,%2,%3}, {%4,%5,%6,%7}, {%8,%9}, {%0,%1,%2,%3};" \
                 : "+f"((d)[0]), "+f"((d)[1]), "+f"((d)[2]), "+f"((d)[3]) \
                 : "r"((a)[0]), "r"((a)[1]), "r"((a)[2]), "r"((a)[3]), \
                   "r"((b)[0]), "r"((b)[1]))

// ---------------------------------------------------------------------------
// Prologue 1: split W into bf16 hi/lo row-major images.
// ---------------------------------------------------------------------------
__global__ void gat_wsplit(const float* __restrict__ W) {
    int t = blockIdx.x * 256 + threadIdx.x;   // 4096 threads, one float4 each
    float4 v = ((const float4*)W)[t];
    unsigned h0, l0, h1, l1;
    split2(v.x, v.y, h0, l0);
    split2(v.z, v.w, h1, l1);
    ((unsigned*)g_wbh4)[t * 2]     = h0;
    ((unsigned*)g_wbh4)[t * 2 + 1] = h1;
    ((unsigned*)g_wbl4)[t * 2]     = l0;
    ((unsigned*)g_wbl4)[t * 2 + 1] = l1;
}

// ---------------------------------------------------------------------------
// Prologue 2: segment starts from sorted dst.
// ---------------------------------------------------------------------------
__global__ void gat_seg(const int* __restrict__ dst, int n_edges, int n_nodes) {
    int i = blockIdx.x * blockDim.x + threadIdx.x;
    if (i < n_edges) {
        int d = dst[i];
        int prev = (i == 0) ? -1 : dst[i - 1];
        for (int n = prev + 1; n <= d; ++n) g_rowstart[n] = i;
        if (i == n_edges - 1)
            for (int n = d + 1; n <= n_nodes; ++n) g_rowstart[n] = n_edges;
    }
}

// ---------------------------------------------------------------------------
// Kernel 1: feat = x @ W^T via mma.sync bf16 (2-term split, 3 passes),
// fp32 accumulate in registers. CTA: 128x128, 8 warps each 32x64.
// Epilogue: fp32 feat store + fused el/er (4-lane shfl reduction).
// ---------------------------------------------------------------------------
__global__ void __launch_bounds__(256) gat_gemm(
    const float* __restrict__ x,
    const float* __restrict__ al, const float* __restrict__ ar, int n_nodes)
{
    extern __shared__ char smem[];
    const uint32_t sb = smem_u32(smem);
    const int tid = threadIdx.x, wid = tid >> 5, lane = tid & 31;
    const int rb = blockIdx.x * BM;

    // ---- stage W hi/lo (float4 copies; LDB=272 is 16B-multiple) ----
    {
        const float4* gh = (const float4*)g_wbh4;
        const float4* gl = (const float4*)g_wbl4;
#pragma unroll
        for (int p = tid; p < 2048; p += 256) {
            int row = p >> 4, j = p & 15;
            *(float4*)(smem + SM_WH + row * LDB + j * 16) = gh[p];
            *(float4*)(smem + SM_WL + row * LDB + j * 16) = gl[p];
        }
    }
    if (tid < FD) {
        ((float*)(smem + SM_ALS))[tid] = al[tid];
        ((float*)(smem + SM_ARS))[tid] = ar[tid];
    }
    // ---- stage x tile -> bf16 hi/lo (thread: row tid>>1, col-half tid&1) ----
    {
        const int row = tid >> 1, half = tid & 1;
        int gr = rb + row; if (gr >= n_nodes) gr = n_nodes - 1;
        const float4* xr = (const float4*)(x + (size_t)gr * FD + half * 64);
        char* dh = smem + SM_XH + row * LDB + half * 128;
        char* dl = smem + SM_XL + row * LDB + half * 128;
#pragma unroll
        for (int j = 0; j < 16; ++j) {
            float4 v = xr[j];
            unsigned h0, l0, h1, l1;
            split2(v.x, v.y, h0, l0);
            split2(v.z, v.w, h1, l1);
            *(unsigned*)(dh + j * 8)     = h0;
            *(unsigned*)(dh + j * 8 + 4) = h1;
            *(unsigned*)(dl + j * 8)     = l0;
            *(unsigned*)(dl + j * 8 + 4) = l1;
        }
    }
    __syncthreads();

    const int wm = wid & 3;       // row block: rows wm*32 .. +31
    const int wn = wid >> 2;      // col block: cols wn*64 .. +63

    // ldmatrix lane-dependent base addresses
    // A (x): matrices m0..m3 = rows(l&15), k-half(l>>4)
    const uint32_t aoff = (uint32_t)(wm * 32 + (lane & 15)) * LDB + (uint32_t)(lane >> 4) * 16;
    const uint32_t aH0 = sb + SM_XH + aoff;
    const uint32_t aH1 = aH0 + 16 * LDB;
    const uint32_t aL0 = sb + SM_XL + aoff;
    const uint32_t aL1 = aL0 + 16 * LDB;
    // B (W): group g2 covers n-tiles {2g2, 2g2+1}; m0,m1 = n..n+7 khalf 0/1; m2,m3 = n+8..
    uint32_t bH[4], bL[4];
#pragma unroll
    for (int g2 = 0; g2 < 4; ++g2) {
        uint32_t nrow = (uint32_t)(wn * 64 + g2 * 16 + ((lane >> 4) * 8) + (lane & 7));
        uint32_t off = nrow * LDB + (uint32_t)((lane >> 3) & 1) * 16;
        bH[g2] = sb + SM_WH + off;
        bL[g2] = sb + SM_WL + off;
    }

    float acc[2][8][4];
#pragma unroll
    for (int m = 0; m < 2; ++m)
#pragma unroll
        for (int nt = 0; nt < 8; ++nt)
#pragma unroll
            for (int q = 0; q < 4; ++q) acc[m][nt][q] = 0.f;

#pragma unroll
    for (int s = 0; s < 8; ++s) {
        const uint32_t kb = s * 32;   // 16 bf16 = 32 bytes
        unsigned ah[2][4], alo[2][4], bh[8][2], bl[8][2];
        LDSM_X4(ah[0][0], ah[0][1], ah[0][2], ah[0][3], aH0 + kb);
        LDSM_X4(ah[1][0], ah[1][1], ah[1][2], ah[1][3], aH1 + kb);
        LDSM_X4(alo[0][0], alo[0][1], alo[0][2], alo[0][3], aL0 + kb);
        LDSM_X4(alo[1][0], alo[1][1], alo[1][2], alo[1][3], aL1 + kb);
#pragma unroll
        for (int g2 = 0; g2 < 4; ++g2) {
            LDSM_X4(bh[2 * g2][0], bh[2 * g2][1], bh[2 * g2 + 1][0], bh[2 * g2 + 1][1], bH[g2] + kb);
            LDSM_X4(bl[2 * g2][0], bl[2 * g2][1], bl[2 * g2 + 1][0], bl[2 * g2 + 1][1], bL[g2] + kb);
        }
#pragma unroll
        for (int m = 0; m < 2; ++m)
#pragma unroll
            for (int nt = 0; nt < 8; ++nt) {
                MMA16816(acc[m][nt], ah[m], bh[nt]);   // hi*hi
                MMA16816(acc[m][nt], ah[m], bl[nt]);   // hi*lo
                MMA16816(acc[m][nt], alo[m], bh[nt]);  // lo*hi
            }
    }

    // ---- epilogue: feat store + fused el/er ----
    const unsigned FULL = 0xffffffffu;
    const float* als = (const float*)(smem + SM_ALS);
    const float* ars = (const float*)(smem + SM_ARS);
    const int cq = (lane & 3) * 2;          // col pair within n-tile

#pragma unroll
    for (int m = 0; m < 2; ++m) {
#pragma unroll
        for (int rh = 0; rh < 2; ++rh) {
            const int grow = rb + wm * 32 + m * 16 + (lane >> 2) + rh * 8;
            const bool ok = grow < n_nodes;
            float pl0 = 0.f, pr0 = 0.f, pl1 = 0.f, pr1 = 0.f;
#pragma unroll
            for (int nt = 0; nt < 8; ++nt) {
                const int c = wn * 64 + nt * 8 + cq;
                const float v0 = acc[m][nt][rh * 2];
                const float v1 = acc[m][nt][rh * 2 + 1];
                if (ok)
                    *(float2*)(g_feat + (size_t)grow * FD + c) = make_float2(v0, v1);
                const float a0 = als[c], a1 = als[c + 1];
                const float b0 = ars[c], b1 = ars[c + 1];
                if (nt < 4) { pl0 = fmaf(v0, a0, fmaf(v1, a1, pl0));
                              pr0 = fmaf(v0, b0, fmaf(v1, b1, pr0)); }
                else        { pl1 = fmaf(v0, a0, fmaf(v1, a1, pl1));
                              pr1 = fmaf(v0, b0, fmaf(v1, b1, pr1)); }
            }
            // reduce across the 4 lanes sharing this row (lane^1, lane^2)
#pragma unroll
            for (int off = 1; off <= 2; off <<= 1) {
                pl0 += __shfl_xor_sync(FULL, pl0, off);
                pr0 += __shfl_xor_sync(FULL, pr0, off);
                pl1 += __shfl_xor_sync(FULL, pl1, off);
                pr1 += __shfl_xor_sync(FULL, pr1, off);
            }
            if (ok && (lane & 3) == 0) {
                const int h0 = 2 * wn, h1 = 2 * wn + 1;
                g_el[grow * NH + h0] = pl0;  g_er[grow * NH + h0] = pr0;
                g_el[grow * NH + h1] = pl1;  g_er[grow * NH + h1] = pr1;
            }
        }
    }
}

// ---------------------------------------------------------------------------
// Kernel 2: single-pass softmax + aggregation (unchanged from R4: 34.7us).
// ---------------------------------------------------------------------------
__global__ void __launch_bounds__(256) gat_agg(
    const int* __restrict__ src, float* __restrict__ out, int n_nodes)
{
    const int lane = threadIdx.x & 31;
    const int n = (blockIdx.x * blockDim.x + threadIdx.x) >> 5;
    if (n >= n_nodes) return;

    const int s = g_rowstart[n];
    const int e = g_rowstart[n + 1];
    const int h = lane >> 3;
    const float ern = g_er[n * NH + h];

    float denom = 0.f;
    float ax = 0.f, ay = 0.f, az = 0.f, aw = 0.f;

#pragma unroll 2
    for (int i = s; i < e; ++i) {
        int sv = __ldg(src + i);
        float lg = __ldg(g_el + sv * NH + h) + ern;
        lg = lg > 0.f ? lg : 0.2f * lg;
        float w = __expf(lg);
        denom += w;
        float4 f = *(const float4*)(g_feat + (size_t)sv * FD + lane * 4);
        ax = fmaf(w, f.x, ax); ay = fmaf(w, f.y, ay);
        az = fmaf(w, f.z, az); aw = fmaf(w, f.w, aw);
    }
    float r = (e > s) ? 1.0f / denom : 0.f;
    *(float4*)(out + (size_t)n * FD + lane * 4) =
        make_float4(ax * r, ay * r, az * r, aw * r);
}

// ---------------------------------------------------------------------------
extern "C" void kernel_launch(void* const* d_in, const int* in_sizes, int n_in,
                              void* d_out, int out_size)
{
    const float* x   = (const float*)d_in[0];
    const float* W   = (const float*)d_in[1];
    const float* al  = (const float*)d_in[2];
    const float* ar  = (const float*)d_in[3];
    const int*   src = (const int*)d_in[4];
    const int*   dst = (const int*)d_in[5];
    float* out = (float*)d_out;

    const int n_nodes = in_sizes[0] / FD;
    const int n_edges = in_sizes[4];

    gat_wsplit<<<16, 256>>>(W);
    gat_seg<<<(n_edges + 255) / 256, 256>>>(dst, n_edges, n_nodes);

    cudaFuncSetAttribute(gat_gemm, cudaFuncAttributeMaxDynamicSharedMemorySize, SM_TOTAL);
    gat_gemm<<<(n_nodes + BM - 1) / BM, 256, SM_TOTAL>>>(x, al, ar, n_nodes);

    gat_agg<<<(n_nodes * 32 + 255) / 256, 256>>>(src, out, n_nodes);
}